// round 7
// baseline (speedup 1.0000x reference)
#include <cuda_runtime.h>
#include <math.h>

#define BB    1024
#define NN    128
#define FEAT  512
#define HID   256

#define ROWS_PER_BLK 64
#define DT_STRIDE    260      // 256 + 4 pad
#define JCHUNK       128
#define ICHUNK       32
#define SMEM_MAIN ((ROWS_PER_BLK*DT_STRIDE + ICHUNK*JCHUNK)*4)

// __device__ scratch (allocation-free rule)
__device__ float g_xp[BB * HID];
__device__ float g_dist[BB * NN];   // fallback distmat store if out has no room
__device__ int   g_lab64;           // 1 => labels really are int64

// ---------------------------------------------------------------------------
// f32x2 helpers (SASS FFMA2 — only reachable via PTX fma.rn.f32x2)
// ---------------------------------------------------------------------------
static __device__ __forceinline__ unsigned long long dup2(float x) {
    unsigned long long r;
    asm("mov.b64 %0, {%1, %1};" : "=l"(r) : "f"(x));
    return r;
}
static __device__ __forceinline__ void ffma2(unsigned long long& d,
                                             unsigned long long a,
                                             unsigned long long b) {
    asm("fma.rn.f32x2 %0, %1, %2, %3;" : "=l"(d) : "l"(a), "l"(b), "l"(d));
}

// ---------------------------------------------------------------------------
// Label dtype detector: interpret the buffer as int32. int64 labels (LE)
// give lab32[2i+1]==0 and lab32[2i] in [0,NN) for all i; random int32 labels
// violate this with probability ~1. Reads only 4KB (safe for either dtype).
// ---------------------------------------------------------------------------
__global__ void detect_labels_kernel(const int* __restrict__ lab32) {
    __shared__ int ok;
    if (threadIdx.x == 0) ok = 1;
    __syncthreads();
    int i = threadIdx.x;              // 0..511
    if (lab32[2 * i + 1] != 0 || (unsigned)lab32[2 * i] >= NN) ok = 0;
    __syncthreads();
    if (threadIdx.x == 0) g_lab64 = ok;
}

// ---------------------------------------------------------------------------
// Kernel A: x_proj = x @ W_proj + b_proj   (1024x512 @ 512x256)
// ---------------------------------------------------------------------------
__global__ void __launch_bounds__(256) proj_kernel(const float* __restrict__ x,
                                                   const float* __restrict__ W,
                                                   const float* __restrict__ bp) {
    __shared__ float xs[64 * 17];
    __shared__ float ws[16 * 65];
    const int tid = threadIdx.x;
    const int tx = tid & 15, ty = tid >> 4;
    const int rb = blockIdx.y * 64, cb = blockIdx.x * 64;

    float acc[4][4] = {};
    for (int kt = 0; kt < FEAT; kt += 16) {
        __syncthreads();
        for (int t = tid; t < 1024; t += 256) {
            int r = t >> 4, kk = t & 15;
            xs[r * 17 + kk] = x[(rb + r) * FEAT + kt + kk];
            int k2 = t >> 6, c = t & 63;
            ws[k2 * 65 + c] = W[(kt + k2) * HID + cb + c];
        }
        __syncthreads();
#pragma unroll
        for (int kk = 0; kk < 16; ++kk) {
            float a[4], b[4];
#pragma unroll
            for (int i = 0; i < 4; i++) a[i] = xs[(ty * 4 + i) * 17 + kk];
#pragma unroll
            for (int j = 0; j < 4; j++) b[j] = ws[kk * 65 + tx * 4 + j];
#pragma unroll
            for (int i = 0; i < 4; i++)
#pragma unroll
                for (int j = 0; j < 4; j++) acc[i][j] += a[i] * b[j];
        }
    }
#pragma unroll
    for (int i = 0; i < 4; i++) {
        int r = rb + ty * 4 + i;
#pragma unroll
        for (int j = 0; j < 4; j++) {
            int c = cb + tx * 4 + j;
            g_xp[r * HID + c] = acc[i][j] + bp[c];
        }
    }
}

// ---------------------------------------------------------------------------
// Kernel B: per block = (center n, 64 batch rows). Writes distmat ONLY.
// dist_sq[b] = sum_j ( sum_i d_i M[i][j] ) * d_j, fused.
// ---------------------------------------------------------------------------
__global__ void __launch_bounds__(256, 2) center_main_kernel(
    const float* __restrict__ means,
    const float* __restrict__ Mg,
    float* __restrict__ distout) {      // nullptr => g_dist
    extern __shared__ float sm[];
    float* Dt = sm;                                   // [64][DT_STRIDE]
    float* Ms = sm + ROWS_PER_BLK * DT_STRIDE;        // [32][128]
    float* dp = distout ? distout : g_dist;

    const int tid = threadIdx.x;
    const int n  = blockIdx.x;
    const int b0 = blockIdx.y * ROWS_PER_BLK;

    // Stage delta tile: Dt[r][i] = x_proj[b0+r][i] - means[n][i]
    for (int t = tid; t < ROWS_PER_BLK * (HID / 4); t += 256) {
        int r = t >> 6, i4 = t & 63;
        float4 v = *(const float4*)&g_xp[(b0 + r) * HID + i4 * 4];
        float4 m = *(const float4*)&means[n * HID + i4 * 4];
        v.x -= m.x; v.y -= m.y; v.z -= m.z; v.w -= m.w;
        *(float4*)&Dt[r * DT_STRIDE + i4 * 4] = v;
    }

    const float* Mbase = Mg + (size_t)n * HID * HID;
    const int cg = tid & 15, rg = tid >> 4;
    const int r0 = rg * 4, c0 = cg * 8;

    float rowpart[4] = {0.f, 0.f, 0.f, 0.f};

    for (int jc = 0; jc < 2; ++jc) {
        const int JC = jc * JCHUNK;
        unsigned long long acc[4][4];
#pragma unroll
        for (int a = 0; a < 4; a++)
#pragma unroll
            for (int p = 0; p < 4; p++) acc[a][p] = 0ull;

        for (int icb = 0; icb < HID; icb += ICHUNK) {
            __syncthreads();   // also orders the Dt fill before first use
            for (int t = tid; t < (ICHUNK * JCHUNK) / 4; t += 256) {
                int kk = t >> 5, c4 = t & 31;
                *(float4*)&Ms[kk * JCHUNK + c4 * 4] =
                    *(const float4*)&Mbase[(size_t)(icb + kk) * HID + JC + c4 * 4];
            }
            __syncthreads();
#pragma unroll 4
            for (int k = 0; k < ICHUNK; ++k) {
                const int ci = icb + k;
                unsigned long long dd0 = dup2(Dt[(r0 + 0) * DT_STRIDE + ci]);
                unsigned long long dd1 = dup2(Dt[(r0 + 1) * DT_STRIDE + ci]);
                unsigned long long dd2 = dup2(Dt[(r0 + 2) * DT_STRIDE + ci]);
                unsigned long long dd3 = dup2(Dt[(r0 + 3) * DT_STRIDE + ci]);
                const ulonglong2* mp =
                    (const ulonglong2*)&Ms[k * JCHUNK + c0];
                ulonglong2 mA = mp[0];
                ulonglong2 mB = mp[1];
                ffma2(acc[0][0], dd0, mA.x); ffma2(acc[0][1], dd0, mA.y);
                ffma2(acc[0][2], dd0, mB.x); ffma2(acc[0][3], dd0, mB.y);
                ffma2(acc[1][0], dd1, mA.x); ffma2(acc[1][1], dd1, mA.y);
                ffma2(acc[1][2], dd1, mB.x); ffma2(acc[1][3], dd1, mB.y);
                ffma2(acc[2][0], dd2, mA.x); ffma2(acc[2][1], dd2, mA.y);
                ffma2(acc[2][2], dd2, mB.x); ffma2(acc[2][3], dd2, mB.y);
                ffma2(acc[3][0], dd3, mA.x); ffma2(acc[3][1], dd3, mA.y);
                ffma2(acc[3][2], dd3, mB.x); ffma2(acc[3][3], dd3, mB.y);
            }
        }
#pragma unroll
        for (int rr = 0; rr < 4; rr++) {
            const float* drow = &Dt[(r0 + rr) * DT_STRIDE + JC + c0];
#pragma unroll
            for (int p = 0; p < 4; p++) {
                float lo = __uint_as_float((unsigned)(acc[rr][p] & 0xffffffffull));
                float hi = __uint_as_float((unsigned)(acc[rr][p] >> 32));
                rowpart[rr] += lo * drow[2 * p] + hi * drow[2 * p + 1];
            }
        }
    }

#pragma unroll
    for (int rr = 0; rr < 4; rr++) {
        float v = rowpart[rr];
        v += __shfl_xor_sync(0xffffffffu, v, 8);
        v += __shfl_xor_sync(0xffffffffu, v, 4);
        v += __shfl_xor_sync(0xffffffffu, v, 2);
        v += __shfl_xor_sync(0xffffffffu, v, 1);
        if ((tid & 15) == 0) {
            int gb = b0 + r0 + rr;
            dp[gb * NN + n] = sqrtf(v + 1e-12f);
        }
    }
}

// ---------------------------------------------------------------------------
// Loss: one block, 1024 threads. Each reads dist[b, label_b] with the
// detected label dtype, deterministic tree reduce, single write to out[0].
// Base constant = (B*(N-1)) masked entries clipped 0 -> 1e-12, / B.
// ---------------------------------------------------------------------------
__global__ void __launch_bounds__(1024) loss_kernel(
    const void* __restrict__ labels_raw,
    const float* __restrict__ distout,     // nullptr => g_dist
    float* __restrict__ out) {
    __shared__ float red[1024];
    const float* dist = distout ? distout : g_dist;
    int b = threadIdx.x;
    int lab = g_lab64 ? (int)((const long long*)labels_raw)[b]
                      : ((const int*)labels_raw)[b];
    float d = dist[b * NN + lab];
    d = fminf(fmaxf(d, 1e-12f), 1e12f);
    red[b] = d;
    __syncthreads();
#pragma unroll
    for (int s = 512; s > 0; s >>= 1) {
        if (b < s) red[b] += red[b + s];
        __syncthreads();
    }
    if (b == 0)
        out[0] = red[0] * (1.0f / (float)BB)
               + (float)((double)(NN - 1) * 1e-12);
}

// ---------------------------------------------------------------------------
extern "C" void kernel_launch(void* const* d_in, const int* in_sizes, int n_in,
                              void* d_out, int out_size) {
    const float* x     = (const float*)d_in[0];
    const void*  lab   = d_in[1];
    const float* W     = (const float*)d_in[2];
    const float* bp    = (const float*)d_in[3];
    const float* means = (const float*)d_in[4];
    const float* Mg    = (const float*)d_in[5];
    float* out = (float*)d_out;
    (void)in_sizes; (void)n_in;

    // Default layout: out = [loss, distmat(B*N)].
    float* distout = out + 1;
    int loss_on = 1;
    if (out_size == BB * NN) { distout = out; loss_on = 0; }   // dist only
    else if (out_size == 1)  { distout = nullptr; }            // loss only

    cudaFuncSetAttribute(center_main_kernel,
                         cudaFuncAttributeMaxDynamicSharedMemorySize, SMEM_MAIN);

    if (loss_on) detect_labels_kernel<<<1, 512>>>((const int*)lab);
    proj_kernel<<<dim3(HID / 64, BB / 64), 256>>>(x, W, bp);
    center_main_kernel<<<dim3(NN, BB / ROWS_PER_BLK), 256, SMEM_MAIN>>>(
        means, Mg, distout);
    if (loss_on) loss_kernel<<<1, 1024>>>(lab, distout, out);
}

// round 11
// speedup vs baseline: 2.4905x; 2.4905x over previous
#include <cuda_runtime.h>
#include <cuda_bf16.h>
#include <math.h>
#include <stdint.h>

#define BB    1024
#define NN    128
#define FEAT  512
#define HID   256

// __device__ scratch (allocation-free rule)
__device__ float          g_xp  [BB * HID];
__device__ __nv_bfloat16  g_xphi[BB * HID];
__device__ __nv_bfloat16  g_xplo[BB * HID];
__device__ __nv_bfloat16  g_Mhi [NN * HID * HID];
__device__ __nv_bfloat16  g_Mlo [NN * HID * HID];
__device__ float          g_v   [NN * HID];
__device__ float          g_c   [NN];
__device__ float          g_part[4 * BB * NN];   // slice = nh*2 + wn_half
__device__ float          g_dist[BB * NN];
__device__ int            g_lab64;

// ===========================================================================
// helpers
// ===========================================================================
static __device__ __forceinline__ uint32_t smem_to_u32(const void* p) {
    uint32_t a;
    asm("{ .reg .u64 t; cvta.to.shared.u64 t, %1; cvt.u32.u64 %0, t; }"
        : "=r"(a) : "l"(p));
    return a;
}
static __device__ __forceinline__ void cp_async16(uint32_t dst, const void* src) {
    asm volatile("cp.async.cg.shared.global [%0], [%1], 16;"
                 :: "r"(dst), "l"(__cvta_generic_to_global(src)) : "memory");
}
#define CP_COMMIT() asm volatile("cp.async.commit_group;" ::: "memory")
#define CP_WAIT0()  asm volatile("cp.async.wait_group 0;" ::: "memory")

static __device__ __forceinline__ void ldm_x4(uint32_t* r, uint32_t addr) {
    asm volatile("ldmatrix.sync.aligned.m8n8.x4.shared.b16 {%0,%1,%2,%3}, [%4];"
                 : "=r"(r[0]), "=r"(r[1]), "=r"(r[2]), "=r"(r[3]) : "r"(addr));
}
static __device__ __forceinline__ void mma16816(float* c, const uint32_t* a,
                                                uint32_t b0, uint32_t b1) {
    asm volatile(
        "mma.sync.aligned.m16n8k16.row.col.f32.bf16.bf16.f32 "
        "{%0,%1,%2,%3}, {%4,%5,%6,%7}, {%8,%9}, {%0,%1,%2,%3};"
        : "+f"(c[0]), "+f"(c[1]), "+f"(c[2]), "+f"(c[3])
        : "r"(a[0]), "r"(a[1]), "r"(a[2]), "r"(a[3]), "r"(b0), "r"(b1));
}
static __device__ __forceinline__ unsigned long long pack4bf(float a, float b,
                                                             float c, float d) {
    __nv_bfloat162 p0 = __floats2bfloat162_rn(a, b);
    __nv_bfloat162 p1 = __floats2bfloat162_rn(c, d);
    unsigned lo = *(unsigned*)&p0, hi = *(unsigned*)&p1;
    unsigned long long r;
    asm("mov.b64 %0, {%1, %2};" : "=l"(r) : "r"(lo), "r"(hi));
    return r;
}

// ===========================================================================
// Label dtype detector (int64 LE: odd words zero, even words < NN)
// ===========================================================================
__global__ void detect_labels_kernel(const int* __restrict__ lab32) {
    __shared__ int ok;
    if (threadIdx.x == 0) ok = 1;
    __syncthreads();
    int i = threadIdx.x;
    if (lab32[2 * i + 1] != 0 || (unsigned)lab32[2 * i] >= NN) ok = 0;
    __syncthreads();
    if (threadIdx.x == 0) g_lab64 = ok;
}

// ===========================================================================
// Kernel A: x_proj = x @ W_proj + b_proj  (fp32, exact)
// ===========================================================================
__global__ void __launch_bounds__(256) proj_kernel(const float* __restrict__ x,
                                                   const float* __restrict__ W,
                                                   const float* __restrict__ bp) {
    __shared__ float xs[64 * 17];
    __shared__ float ws[16 * 65];
    const int tid = threadIdx.x;
    const int tx = tid & 15, ty = tid >> 4;
    const int rb = blockIdx.y * 64, cb = blockIdx.x * 64;

    float acc[4][4] = {};
    for (int kt = 0; kt < FEAT; kt += 16) {
        __syncthreads();
        for (int t = tid; t < 1024; t += 256) {
            int r = t >> 4, kk = t & 15;
            xs[r * 17 + kk] = x[(rb + r) * FEAT + kt + kk];
            int k2 = t >> 6, c = t & 63;
            ws[k2 * 65 + c] = W[(kt + k2) * HID + cb + c];
        }
        __syncthreads();
#pragma unroll
        for (int kk = 0; kk < 16; ++kk) {
            float a[4], b[4];
#pragma unroll
            for (int i = 0; i < 4; i++) a[i] = xs[(ty * 4 + i) * 17 + kk];
#pragma unroll
            for (int j = 0; j < 4; j++) b[j] = ws[kk * 65 + tx * 4 + j];
#pragma unroll
            for (int i = 0; i < 4; i++)
#pragma unroll
                for (int j = 0; j < 4; j++) acc[i][j] += a[i] * b[j];
        }
    }
#pragma unroll
    for (int i = 0; i < 4; i++) {
        int r = rb + ty * 4 + i;
#pragma unroll
        for (int j = 0; j < 4; j++) {
            int c = cb + tx * 4 + j;
            g_xp[r * HID + c] = acc[i][j] + bp[c];
        }
    }
}

// ===========================================================================
// prep: bf16 hi/lo conversions (once per run)
// ===========================================================================
__global__ void __launch_bounds__(256) conv_x_kernel() {
    int i4 = blockIdx.x * 256 + threadIdx.x;          // 65536 float4 groups
    float4 v = *(const float4*)&g_xp[i4 * 4];
    float h0 = __bfloat162float(__float2bfloat16_rn(v.x));
    float h1 = __bfloat162float(__float2bfloat16_rn(v.y));
    float h2 = __bfloat162float(__float2bfloat16_rn(v.z));
    float h3 = __bfloat162float(__float2bfloat16_rn(v.w));
    *(unsigned long long*)&g_xphi[i4 * 4] = pack4bf(h0, h1, h2, h3);
    *(unsigned long long*)&g_xplo[i4 * 4] =
        pack4bf(v.x - h0, v.y - h1, v.z - h2, v.w - h3);
}

__global__ void __launch_bounds__(256) conv_m_kernel(const float* __restrict__ Mg) {
    // 8388608 elems = 2097152 float4; grid 1024 x 256 threads x 8 iters
    size_t base = (size_t)blockIdx.x * 2048 + threadIdx.x;
#pragma unroll
    for (int it = 0; it < 8; ++it) {
        size_t i4 = base + (size_t)it * 256;
        float4 v = *(const float4*)&Mg[i4 * 4];
        float h0 = __bfloat162float(__float2bfloat16_rn(v.x));
        float h1 = __bfloat162float(__float2bfloat16_rn(v.y));
        float h2 = __bfloat162float(__float2bfloat16_rn(v.z));
        float h3 = __bfloat162float(__float2bfloat16_rn(v.w));
        *(unsigned long long*)&g_Mhi[i4 * 4] = pack4bf(h0, h1, h2, h3);
        *(unsigned long long*)&g_Mlo[i4 * 4] =
            pack4bf(v.x - h0, v.y - h1, v.z - h2, v.w - h3);
    }
}

// v_n = M_n mu_n (fp32), c_n = mu_n . v_n
__global__ void __launch_bounds__(256) vc_kernel(const float* __restrict__ means,
                                                 const float* __restrict__ Mg) {
    __shared__ float mu[HID];
    __shared__ float sv[HID];
    __shared__ float red[256];
    const int n = blockIdx.x, tid = threadIdx.x;
    const int wid = tid >> 5, lane = tid & 31;
    mu[tid] = means[n * HID + tid];
    __syncthreads();
    const float* Mn = Mg + (size_t)n * HID * HID;
    for (int rr = 0; rr < 32; ++rr) {
        int row = wid * 32 + rr;
        const float* mr = Mn + (size_t)row * HID;
        float s = 0.f;
#pragma unroll
        for (int p = 0; p < 2; ++p) {
            int i4 = lane + p * 32;
            float4 a = *(const float4*)&mr[i4 * 4];
            float4 b = *(const float4*)&mu[i4 * 4];
            s += a.x * b.x + a.y * b.y + a.z * b.z + a.w * b.w;
        }
#pragma unroll
        for (int m = 16; m > 0; m >>= 1) s += __shfl_xor_sync(~0u, s, m);
        if (lane == 0) sv[row] = s;
    }
    __syncthreads();
    g_v[n * HID + tid] = sv[tid];
    red[tid] = mu[tid] * sv[tid];
    __syncthreads();
#pragma unroll
    for (int s = 128; s > 0; s >>= 1) {
        if (tid < s) red[tid] += red[tid + s];
        __syncthreads();
    }
    if (tid == 0) g_c[n] = red[0];
}

// ===========================================================================
// Main kernel: Y = X_p @ M_n (128-row tile x 128-col half, K=256) via
// mma.sync bf16 3-way split; epilogue folds sum_j x*(Y - 2v) in fp32.
// grid = (NN, BB/128, 2); 256 threads = 8 warps (4m x 2n), warp = 32x64.
// Each warp writes its own partial slice (nh*2 + wn_half) — NO shared rows.
// ===========================================================================
#define KC       64
#define STG_B    65536

__global__ void __launch_bounds__(256) center_mma_kernel() {
    extern __shared__ char smem[];
    const uint32_t sbase = smem_to_u32(smem);

    const int tid = threadIdx.x;
    const int wid = tid >> 5, lane = tid & 31;
    const int n  = blockIdx.x;
    const int b0 = blockIdx.y * 128;
    const int nh = blockIdx.z;                  // 0/1 column half

    const int wm = (wid & 3) * 32;              // warp m offset (0..96)
    const int wnh = wid >> 2;                   // warp n half (0/1)
    const int wn = wnh * 64;
    const int lr = lane & 15, lh = lane >> 4;
    const int gr = lane >> 2, qc = (lane & 3) * 2;

    // staging bases (bf16 elements)
    const __nv_bfloat16* Ahg = g_xphi + (size_t)b0 * HID;
    const __nv_bfloat16* Alg = g_xplo + (size_t)b0 * HID;
    const __nv_bfloat16* Bhg = g_Mhi + ((size_t)n * HID + nh * 128) * HID;
    const __nv_bfloat16* Blg = g_Mlo + ((size_t)n * HID + nh * 128) * HID;

    // stage one K-chunk (k0 = kc*64) into stage buffer s
    auto stage = [&](int kc, int s) {
        const int k0 = kc * KC;
        const uint32_t sb = sbase + s * STG_B;
#pragma unroll
        for (int it = 0; it < 16; ++it) {
            int t = tid + it * 256;             // 0..4095
            int buf = t >> 10;                  // 0 Ah,1 Al,2 Bh,3 Bl
            int rem = t & 1023;
            int r = rem >> 3, c16 = rem & 7;
            const __nv_bfloat16* src =
                (buf == 0 ? Ahg : buf == 1 ? Alg : buf == 2 ? Bhg : Blg)
                + (size_t)r * HID + k0 + c16 * 8;
            uint32_t dst = sb + ((buf << 10) + (r << 3) + (c16 ^ (r & 7))) * 16;
            cp_async16(dst, src);
        }
        CP_COMMIT();
    };

    float C[2][8][4];
#pragma unroll
    for (int a = 0; a < 2; a++)
#pragma unroll
        for (int b = 0; b < 8; b++)
#pragma unroll
            for (int c = 0; c < 4; c++) C[a][b][c] = 0.f;

    stage(0, 0);
    CP_WAIT0();
    __syncthreads();

    for (int kc = 0; kc < 4; ++kc) {
        if (kc < 3) stage(kc + 1, (kc + 1) & 1);
        const uint32_t sb = sbase + (kc & 1) * STG_B;
        const uint32_t oAh = sb, oAl = sb + 16384, oBh = sb + 32768,
                       oBl = sb + 49152;
#pragma unroll
        for (int ks = 0; ks < 4; ++ks) {
            uint32_t ah[2][4], al[2][4], bh[4][4], bl[4][4];
#pragma unroll
            for (int mt = 0; mt < 2; ++mt) {
                int row = wm + mt * 16 + lr;
                uint32_t co = (uint32_t)(((2 * ks + lh) ^ (row & 7)) * 16 +
                                         row * 128);
                ldm_x4(ah[mt], oAh + co);
                ldm_x4(al[mt], oAl + co);
            }
#pragma unroll
            for (int nt = 0; nt < 4; ++nt) {
                int row = wn + nt * 16 + lr;
                uint32_t co = (uint32_t)(((2 * ks + lh) ^ (row & 7)) * 16 +
                                         row * 128);
                ldm_x4(bh[nt], oBh + co);
                ldm_x4(bl[nt], oBl + co);
            }
#pragma unroll
            for (int mt = 0; mt < 2; ++mt)
#pragma unroll
                for (int nt = 0; nt < 4; ++nt) {
                    mma16816(C[mt][2 * nt],     ah[mt], bh[nt][0], bh[nt][2]);
                    mma16816(C[mt][2 * nt + 1], ah[mt], bh[nt][1], bh[nt][3]);
                    mma16816(C[mt][2 * nt],     al[mt], bh[nt][0], bh[nt][2]);
                    mma16816(C[mt][2 * nt + 1], al[mt], bh[nt][1], bh[nt][3]);
                    mma16816(C[mt][2 * nt],     ah[mt], bl[nt][0], bl[nt][2]);
                    mma16816(C[mt][2 * nt + 1], ah[mt], bl[nt][1], bl[nt][3]);
                }
        }
        if (kc < 3) {
            CP_WAIT0();
            __syncthreads();
        }
    }

    // epilogue: rs[row] = sum_{j in this warp's 64 cols} x[row][j]*(Y[row][j]-2v[j])
    // slice = nh*2 + wnh  — every (slice,row,n) written by exactly one warp.
    const float* vn = g_v + n * HID;
    float* part = g_part + (size_t)(nh * 2 + wnh) * BB * NN;
#pragma unroll
    for (int mt = 0; mt < 2; ++mt) {
        int row0 = b0 + wm + mt * 16 + gr;
        int row1 = row0 + 8;
        float rs0 = 0.f, rs1 = 0.f;
#pragma unroll
        for (int nt = 0; nt < 8; ++nt) {
            int j = nh * 128 + wn + nt * 8 + qc;
            float2 v2  = *(const float2*)&vn[j];
            float2 x0  = *(const float2*)&g_xp[(size_t)row0 * HID + j];
            float2 x1  = *(const float2*)&g_xp[(size_t)row1 * HID + j];
            rs0 += x0.x * (C[mt][nt][0] - 2.f * v2.x)
                 + x0.y * (C[mt][nt][1] - 2.f * v2.y);
            rs1 += x1.x * (C[mt][nt][2] - 2.f * v2.x)
                 + x1.y * (C[mt][nt][3] - 2.f * v2.y);
        }
        rs0 += __shfl_xor_sync(~0u, rs0, 1);
        rs0 += __shfl_xor_sync(~0u, rs0, 2);
        rs1 += __shfl_xor_sync(~0u, rs1, 1);
        rs1 += __shfl_xor_sync(~0u, rs1, 2);
        if ((lane & 3) == 0) {
            part[(size_t)row0 * NN + n] = rs0;
            part[(size_t)row1 * NN + n] = rs1;
        }
    }
}

// ===========================================================================
// finalize: dist = sqrt(sum of 4 partial slices + c_n + 1e-12)
// ===========================================================================
__global__ void __launch_bounds__(256) finalize_kernel(float* __restrict__ distout) {
    float* dp = distout ? distout : g_dist;
    int idx = blockIdx.x * 256 + threadIdx.x;     // 131072
    int nn = idx & (NN - 1);
    float dsq = g_part[idx] + g_part[BB * NN + idx]
              + g_part[2 * BB * NN + idx] + g_part[3 * BB * NN + idx]
              + g_c[nn];
    dp[idx] = sqrtf(dsq + 1e-12f);
}

// ===========================================================================
// Loss: single block, deterministic tree reduce over dist[b, label_b].
// ===========================================================================
__global__ void __launch_bounds__(1024) loss_kernel(
    const void* __restrict__ labels_raw,
    const float* __restrict__ distout,
    float* __restrict__ out) {
    __shared__ float red[1024];
    const float* dist = distout ? distout : g_dist;
    int b = threadIdx.x;
    int lab = g_lab64 ? (int)((const long long*)labels_raw)[b]
                      : ((const int*)labels_raw)[b];
    float d = dist[b * NN + lab];
    d = fminf(fmaxf(d, 1e-12f), 1e12f);
    red[b] = d;
    __syncthreads();
#pragma unroll
    for (int s = 512; s > 0; s >>= 1) {
        if (b < s) red[b] += red[b + s];
        __syncthreads();
    }
    if (b == 0)
        out[0] = red[0] * (1.0f / (float)BB) + (float)((double)(NN - 1) * 1e-12);
}

// ===========================================================================
extern "C" void kernel_launch(void* const* d_in, const int* in_sizes, int n_in,
                              void* d_out, int out_size) {
    const float* x     = (const float*)d_in[0];
    const void*  lab   = d_in[1];
    const float* W     = (const float*)d_in[2];
    const float* bp    = (const float*)d_in[3];
    const float* means = (const float*)d_in[4];
    const float* Mg    = (const float*)d_in[5];
    float* out = (float*)d_out;
    (void)in_sizes; (void)n_in;

    float* distout = out + 1;
    int loss_on = 1;
    if (out_size == BB * NN) { distout = out; loss_on = 0; }
    else if (out_size == 1)  { distout = nullptr; }

    cudaFuncSetAttribute(center_mma_kernel,
                         cudaFuncAttributeMaxDynamicSharedMemorySize,
                         2 * STG_B);

    if (loss_on) detect_labels_kernel<<<1, 512>>>((const int*)lab);
    proj_kernel<<<dim3(HID / 64, BB / 64), 256>>>(x, W, bp);
    conv_x_kernel<<<(BB * HID / 4) / 256, 256>>>();
    conv_m_kernel<<<1024, 256>>>(Mg);
    vc_kernel<<<NN, 256>>>(means, Mg);
    center_mma_kernel<<<dim3(NN, BB / 128, 2), 256, 2 * STG_B>>>();
    finalize_kernel<<<(BB * NN) / 256, 256>>>(distout);
    if (loss_on) loss_kernel<<<1, 1024>>>(lab, distout, out);
}

// round 12
// speedup vs baseline: 3.9541x; 1.5877x over previous
#include <cuda_runtime.h>
#include <cuda_bf16.h>
#include <math.h>
#include <stdint.h>

#define BB    1024
#define NN    128
#define FEAT  512
#define HID   256

// __device__ scratch (allocation-free rule)
__device__ float          g_xp  [BB * HID];
__device__ __nv_bfloat16  g_xphi[BB * HID];
__device__ __nv_bfloat16  g_xplo[BB * HID];
__device__ __nv_bfloat16  g_Mhi [NN * HID * HID];
__device__ float          g_v   [NN * HID];
__device__ float          g_c   [NN];
__device__ float          g_part[4 * BB * NN];   // slice = nh*2 + wn_half
__device__ float          g_dist[BB * NN];
__device__ int            g_lab64;

// ===========================================================================
// helpers
// ===========================================================================
static __device__ __forceinline__ uint32_t smem_to_u32(const void* p) {
    uint32_t a;
    asm("{ .reg .u64 t; cvta.to.shared.u64 t, %1; cvt.u32.u64 %0, t; }"
        : "=r"(a) : "l"(p));
    return a;
}
static __device__ __forceinline__ void cp_async16(uint32_t dst, const void* src) {
    asm volatile("cp.async.cg.shared.global [%0], [%1], 16;"
                 :: "r"(dst), "l"(__cvta_generic_to_global(src)) : "memory");
}
#define CP_COMMIT() asm volatile("cp.async.commit_group;" ::: "memory")
#define CP_WAIT0()  asm volatile("cp.async.wait_group 0;" ::: "memory")

static __device__ __forceinline__ void ldm_x4(uint32_t* r, uint32_t addr) {
    asm volatile("ldmatrix.sync.aligned.m8n8.x4.shared.b16 {%0,%1,%2,%3}, [%4];"
                 : "=r"(r[0]), "=r"(r[1]), "=r"(r[2]), "=r"(r[3]) : "r"(addr));
}
static __device__ __forceinline__ void mma16816(float* c, const uint32_t* a,
                                                uint32_t b0, uint32_t b1) {
    asm volatile(
        "mma.sync.aligned.m16n8k16.row.col.f32.bf16.bf16.f32 "
        "{%0,%1,%2,%3}, {%4,%5,%6,%7}, {%8,%9}, {%0,%1,%2,%3};"
        : "+f"(c[0]), "+f"(c[1]), "+f"(c[2]), "+f"(c[3])
        : "r"(a[0]), "r"(a[1]), "r"(a[2]), "r"(a[3]), "r"(b0), "r"(b1));
}
static __device__ __forceinline__ unsigned long long pack4bf(float a, float b,
                                                             float c, float d) {
    __nv_bfloat162 p0 = __floats2bfloat162_rn(a, b);
    __nv_bfloat162 p1 = __floats2bfloat162_rn(c, d);
    unsigned lo = *(unsigned*)&p0, hi = *(unsigned*)&p1;
    unsigned long long r;
    asm("mov.b64 %0, {%1, %2};" : "=l"(r) : "r"(lo), "r"(hi));
    return r;
}

// ===========================================================================
// Label dtype detector (int64 LE: odd words zero, even words < NN)
// ===========================================================================
__global__ void detect_labels_kernel(const int* __restrict__ lab32) {
    __shared__ int ok;
    if (threadIdx.x == 0) ok = 1;
    __syncthreads();
    int i = threadIdx.x;
    if (lab32[2 * i + 1] != 0 || (unsigned)lab32[2 * i] >= NN) ok = 0;
    __syncthreads();
    if (threadIdx.x == 0) g_lab64 = ok;
}

// ===========================================================================
// Kernel A: x_proj = x @ W_proj + b_proj (fp32) + fused hi/lo bf16 split
// ===========================================================================
__global__ void __launch_bounds__(256) proj_kernel(const float* __restrict__ x,
                                                   const float* __restrict__ W,
                                                   const float* __restrict__ bp) {
    __shared__ float xs[64 * 17];
    __shared__ float ws[16 * 65];
    const int tid = threadIdx.x;
    const int tx = tid & 15, ty = tid >> 4;
    const int rb = blockIdx.y * 64, cb = blockIdx.x * 64;

    float acc[4][4] = {};
    for (int kt = 0; kt < FEAT; kt += 16) {
        __syncthreads();
        for (int t = tid; t < 1024; t += 256) {
            int r = t >> 4, kk = t & 15;
            xs[r * 17 + kk] = x[(rb + r) * FEAT + kt + kk];
            int k2 = t >> 6, c = t & 63;
            ws[k2 * 65 + c] = W[(kt + k2) * HID + cb + c];
        }
        __syncthreads();
#pragma unroll
        for (int kk = 0; kk < 16; ++kk) {
            float a[4], b[4];
#pragma unroll
            for (int i = 0; i < 4; i++) a[i] = xs[(ty * 4 + i) * 17 + kk];
#pragma unroll
            for (int j = 0; j < 4; j++) b[j] = ws[kk * 65 + tx * 4 + j];
#pragma unroll
            for (int i = 0; i < 4; i++)
#pragma unroll
                for (int j = 0; j < 4; j++) acc[i][j] += a[i] * b[j];
        }
    }
#pragma unroll
    for (int i = 0; i < 4; i++) {
        int r = rb + ty * 4 + i;
#pragma unroll
        for (int j = 0; j < 4; j++) {
            int c = cb + tx * 4 + j;
            float val = acc[i][j] + bp[c];
            g_xp[r * HID + c] = val;
            float h = __bfloat162float(__float2bfloat16_rn(val));
            g_xphi[r * HID + c] = __float2bfloat16_rn(val);
            g_xplo[r * HID + c] = __float2bfloat16_rn(val - h);
        }
    }
}

// ===========================================================================
// prep: M -> bf16 hi only (the hi*lo cross term is dropped; see analysis)
// ===========================================================================
__global__ void __launch_bounds__(256) conv_m_kernel(const float* __restrict__ Mg) {
    size_t base = (size_t)blockIdx.x * 2048 + threadIdx.x;
#pragma unroll
    for (int it = 0; it < 8; ++it) {
        size_t i4 = base + (size_t)it * 256;
        float4 v = *(const float4*)&Mg[i4 * 4];
        float h0 = __bfloat162float(__float2bfloat16_rn(v.x));
        float h1 = __bfloat162float(__float2bfloat16_rn(v.y));
        float h2 = __bfloat162float(__float2bfloat16_rn(v.z));
        float h3 = __bfloat162float(__float2bfloat16_rn(v.w));
        *(unsigned long long*)&g_Mhi[i4 * 4] = pack4bf(h0, h1, h2, h3);
    }
}

// v_n = M_n mu_n (fp32), c_n = mu_n . v_n
__global__ void __launch_bounds__(256) vc_kernel(const float* __restrict__ means,
                                                 const float* __restrict__ Mg) {
    __shared__ float mu[HID];
    __shared__ float sv[HID];
    __shared__ float red[256];
    const int n = blockIdx.x, tid = threadIdx.x;
    const int wid = tid >> 5, lane = tid & 31;
    mu[tid] = means[n * HID + tid];
    __syncthreads();
    const float* Mn = Mg + (size_t)n * HID * HID;
    for (int rr = 0; rr < 32; ++rr) {
        int row = wid * 32 + rr;
        const float* mr = Mn + (size_t)row * HID;
        float s = 0.f;
#pragma unroll
        for (int p = 0; p < 2; ++p) {
            int i4 = lane + p * 32;
            float4 a = *(const float4*)&mr[i4 * 4];
            float4 b = *(const float4*)&mu[i4 * 4];
            s += a.x * b.x + a.y * b.y + a.z * b.z + a.w * b.w;
        }
#pragma unroll
        for (int m = 16; m > 0; m >>= 1) s += __shfl_xor_sync(~0u, s, m);
        if (lane == 0) sv[row] = s;
    }
    __syncthreads();
    g_v[n * HID + tid] = sv[tid];
    red[tid] = mu[tid] * sv[tid];
    __syncthreads();
#pragma unroll
    for (int s = 128; s > 0; s >>= 1) {
        if (tid < s) red[tid] += red[tid + s];
        __syncthreads();
    }
    if (tid == 0) g_c[n] = red[0];
}

// ===========================================================================
// Main kernel: Y = (Xh + Xl) @ Mh_n (2-term split); epilogue folds
// sum_j x*(Y - 2v) in fp32. grid = (NN, BB/128, 2); 8 warps (4m x 2n).
// SMEM/stage: Ah|Al (128x64 each) + Bh (128x64) = 48KB, double-buffered
// = 96KB -> 2 CTAs/SM. XOR-swizzled rows for conflict-free ldmatrix.
// ===========================================================================
#define KC       64
#define STG_B    49152

__global__ void __launch_bounds__(256, 2) center_mma_kernel() {
    extern __shared__ char smem[];
    const uint32_t sbase = smem_to_u32(smem);

    const int tid = threadIdx.x;
    const int wid = tid >> 5, lane = tid & 31;
    const int n  = blockIdx.x;
    const int b0 = blockIdx.y * 128;
    const int nh = blockIdx.z;                  // 0/1 column half

    const int wm = (wid & 3) * 32;              // warp m offset (0..96)
    const int wnh = wid >> 2;                   // warp n half (0/1)
    const int wn = wnh * 64;
    const int lr = lane & 15, lh = lane >> 4;
    const int gr = lane >> 2, qc = (lane & 3) * 2;

    const __nv_bfloat16* Ahg = g_xphi + (size_t)b0 * HID;
    const __nv_bfloat16* Alg = g_xplo + (size_t)b0 * HID;
    const __nv_bfloat16* Bhg = g_Mhi + ((size_t)n * HID + nh * 128) * HID;

    // stage one K-chunk (k0 = kc*64) into stage buffer s
    auto stage = [&](int kc, int s) {
        const int k0 = kc * KC;
        const uint32_t sb = sbase + s * STG_B;
#pragma unroll
        for (int it = 0; it < 12; ++it) {
            int t = tid + it * 256;             // 0..3071
            int buf = t >> 10;                  // 0 Ah, 1 Al, 2 Bh
            int rem = t & 1023;
            int r = rem >> 3, c16 = rem & 7;
            const __nv_bfloat16* src =
                (buf == 0 ? Ahg : buf == 1 ? Alg : Bhg)
                + (size_t)r * HID + k0 + c16 * 8;
            uint32_t dst = sb + ((buf << 10) + (r << 3) + (c16 ^ (r & 7))) * 16;
            cp_async16(dst, src);
        }
        CP_COMMIT();
    };

    float C[2][8][4];
#pragma unroll
    for (int a = 0; a < 2; a++)
#pragma unroll
        for (int b = 0; b < 8; b++)
#pragma unroll
            for (int c = 0; c < 4; c++) C[a][b][c] = 0.f;

    stage(0, 0);
    CP_WAIT0();
    __syncthreads();

    for (int kc = 0; kc < 4; ++kc) {
        if (kc < 3) stage(kc + 1, (kc + 1) & 1);
        const uint32_t sb = sbase + (kc & 1) * STG_B;
        const uint32_t oAh = sb, oAl = sb + 16384, oBh = sb + 32768;
#pragma unroll
        for (int ks = 0; ks < 4; ++ks) {
            uint32_t ah[2][4], al[2][4], bh[4][4];
#pragma unroll
            for (int mt = 0; mt < 2; ++mt) {
                int row = wm + mt * 16 + lr;
                uint32_t co = (uint32_t)(((2 * ks + lh) ^ (row & 7)) * 16 +
                                         row * 128);
                ldm_x4(ah[mt], oAh + co);
                ldm_x4(al[mt], oAl + co);
            }
#pragma unroll
            for (int nt = 0; nt < 4; ++nt) {
                int row = wn + nt * 16 + lr;
                uint32_t co = (uint32_t)(((2 * ks + lh) ^ (row & 7)) * 16 +
                                         row * 128);
                ldm_x4(bh[nt], oBh + co);
            }
#pragma unroll
            for (int mt = 0; mt < 2; ++mt)
#pragma unroll
                for (int nt = 0; nt < 4; ++nt) {
                    mma16816(C[mt][2 * nt],     ah[mt], bh[nt][0], bh[nt][2]);
                    mma16816(C[mt][2 * nt + 1], ah[mt], bh[nt][1], bh[nt][3]);
                    mma16816(C[mt][2 * nt],     al[mt], bh[nt][0], bh[nt][2]);
                    mma16816(C[mt][2 * nt + 1], al[mt], bh[nt][1], bh[nt][3]);
                }
        }
        if (kc < 3) {
            CP_WAIT0();
            __syncthreads();
        }
    }

    // epilogue: rs[row] = sum_{j in warp's 64 cols} x[row][j]*(Y[row][j]-2v[j])
    const float* vn = g_v + n * HID;
    float* part = g_part + (size_t)(nh * 2 + wnh) * BB * NN;
#pragma unroll
    for (int mt = 0; mt < 2; ++mt) {
        int row0 = b0 + wm + mt * 16 + gr;
        int row1 = row0 + 8;
        float rs0 = 0.f, rs1 = 0.f;
#pragma unroll
        for (int nt = 0; nt < 8; ++nt) {
            int j = nh * 128 + wn + nt * 8 + qc;
            float2 v2  = *(const float2*)&vn[j];
            float2 x0  = *(const float2*)&g_xp[(size_t)row0 * HID + j];
            float2 x1  = *(const float2*)&g_xp[(size_t)row1 * HID + j];
            rs0 += x0.x * (C[mt][nt][0] - 2.f * v2.x)
                 + x0.y * (C[mt][nt][1] - 2.f * v2.y);
            rs1 += x1.x * (C[mt][nt][2] - 2.f * v2.x)
                 + x1.y * (C[mt][nt][3] - 2.f * v2.y);
        }
        rs0 += __shfl_xor_sync(~0u, rs0, 1);
        rs0 += __shfl_xor_sync(~0u, rs0, 2);
        rs1 += __shfl_xor_sync(~0u, rs1, 1);
        rs1 += __shfl_xor_sync(~0u, rs1, 2);
        if ((lane & 3) == 0) {
            part[(size_t)row0 * NN + n] = rs0;
            part[(size_t)row1 * NN + n] = rs1;
        }
    }
}

// ===========================================================================
// finalize: dist = sqrt(sum of 4 partial slices + c_n + 1e-12)
// ===========================================================================
__global__ void __launch_bounds__(256) finalize_kernel(float* __restrict__ distout) {
    float* dp = distout ? distout : g_dist;
    int idx = blockIdx.x * 256 + threadIdx.x;     // 131072
    int nn = idx & (NN - 1);
    float dsq = g_part[idx] + g_part[BB * NN + idx]
              + g_part[2 * BB * NN + idx] + g_part[3 * BB * NN + idx]
              + g_c[nn];
    dp[idx] = sqrtf(dsq + 1e-12f);
}

// ===========================================================================
// Loss: single block, deterministic tree reduce over dist[b, label_b].
// ===========================================================================
__global__ void __launch_bounds__(1024) loss_kernel(
    const void* __restrict__ labels_raw,
    const float* __restrict__ distout,
    float* __restrict__ out) {
    __shared__ float red[1024];
    const float* dist = distout ? distout : g_dist;
    int b = threadIdx.x;
    int lab = g_lab64 ? (int)((const long long*)labels_raw)[b]
                      : ((const int*)labels_raw)[b];
    float d = dist[b * NN + lab];
    d = fminf(fmaxf(d, 1e-12f), 1e12f);
    red[b] = d;
    __syncthreads();
#pragma unroll
    for (int s = 512; s > 0; s >>= 1) {
        if (b < s) red[b] += red[b + s];
        __syncthreads();
    }
    if (b == 0)
        out[0] = red[0] * (1.0f / (float)BB) + (float)((double)(NN - 1) * 1e-12);
}

// ===========================================================================
extern "C" void kernel_launch(void* const* d_in, const int* in_sizes, int n_in,
                              void* d_out, int out_size) {
    const float* x     = (const float*)d_in[0];
    const void*  lab   = d_in[1];
    const float* W     = (const float*)d_in[2];
    const float* bp    = (const float*)d_in[3];
    const float* means = (const float*)d_in[4];
    const float* Mg    = (const float*)d_in[5];
    float* out = (float*)d_out;
    (void)in_sizes; (void)n_in;

    float* distout = out + 1;
    int loss_on = 1;
    if (out_size == BB * NN) { distout = out; loss_on = 0; }
    else if (out_size == 1)  { distout = nullptr; }

    cudaFuncSetAttribute(center_mma_kernel,
                         cudaFuncAttributeMaxDynamicSharedMemorySize,
                         2 * STG_B);

    if (loss_on) detect_labels_kernel<<<1, 512>>>((const int*)lab);
    conv_m_kernel<<<1024, 256>>>(Mg);
    proj_kernel<<<dim3(HID / 64, BB / 64), 256>>>(x, W, bp);
    vc_kernel<<<NN, 256>>>(means, Mg);
    center_mma_kernel<<<dim3(NN, BB / 128, 2), 256, 2 * STG_B>>>();
    finalize_kernel<<<(BB * NN) / 256, 256>>>(distout);
    if (loss_on) loss_kernel<<<1, 1024>>>(lab, distout, out);
}

// round 15
// speedup vs baseline: 4.0449x; 1.0230x over previous
#include <cuda_runtime.h>
#include <cuda_bf16.h>
#include <math.h>
#include <stdint.h>

#define BB    1024
#define NN    128
#define FEAT  512
#define HID   256

// __device__ scratch (allocation-free rule)
__device__ float          g_xp  [BB * HID];
__device__ __nv_bfloat16  g_xphi[BB * HID];
__device__ __nv_bfloat16  g_xplo[BB * HID];
__device__ __nv_bfloat16  g_Mhi [NN * HID * HID];
__device__ float          g_v   [NN * HID];
__device__ float          g_c   [NN];
__device__ float          g_part[4 * BB * NN];   // slice = nh*2 + wn_half
__device__ float          g_dist[BB * NN];
__device__ int            g_lab64;

// ===========================================================================
// helpers
// ===========================================================================
static __device__ __forceinline__ uint32_t smem_to_u32(const void* p) {
    uint32_t a;
    asm("{ .reg .u64 t; cvta.to.shared.u64 t, %1; cvt.u32.u64 %0, t; }"
        : "=r"(a) : "l"(p));
    return a;
}
static __device__ __forceinline__ void cp_async16(uint32_t dst, const void* src) {
    asm volatile("cp.async.cg.shared.global [%0], [%1], 16;"
                 :: "r"(dst), "l"(__cvta_generic_to_global(src)) : "memory");
}
#define CP_COMMIT() asm volatile("cp.async.commit_group;" ::: "memory")
#define CP_WAIT0()  asm volatile("cp.async.wait_group 0;" ::: "memory")

static __device__ __forceinline__ void ldm_x4(uint32_t* r, uint32_t addr) {
    asm volatile("ldmatrix.sync.aligned.m8n8.x4.shared.b16 {%0,%1,%2,%3}, [%4];"
                 : "=r"(r[0]), "=r"(r[1]), "=r"(r[2]), "=r"(r[3]) : "r"(addr));
}
static __device__ __forceinline__ void mma16816(float* c, const uint32_t* a,
                                                uint32_t b0, uint32_t b1) {
    asm volatile(
        "mma.sync.aligned.m16n8k16.row.col.f32.bf16.bf16.f32 "
        "{%0,%1,%2,%3}, {%4,%5,%6,%7}, {%8,%9}, {%0,%1,%2,%3};"
        : "+f"(c[0]), "+f"(c[1]), "+f"(c[2]), "+f"(c[3])
        : "r"(a[0]), "r"(a[1]), "r"(a[2]), "r"(a[3]), "r"(b0), "r"(b1));
}
static __device__ __forceinline__ unsigned long long pack4bf(float a, float b,
                                                             float c, float d) {
    __nv_bfloat162 p0 = __floats2bfloat162_rn(a, b);
    __nv_bfloat162 p1 = __floats2bfloat162_rn(c, d);
    unsigned lo = *(unsigned*)&p0, hi = *(unsigned*)&p1;
    unsigned long long r;
    asm("mov.b64 %0, {%1, %2};" : "=l"(r) : "r"(lo), "r"(hi));
    return r;
}

// ===========================================================================
// Label dtype detector (int64 LE: odd words zero, even words < NN)
// ===========================================================================
__global__ void detect_labels_kernel(const int* __restrict__ lab32) {
    __shared__ int ok;
    if (threadIdx.x == 0) ok = 1;
    __syncthreads();
    int i = threadIdx.x;
    if (lab32[2 * i + 1] != 0 || (unsigned)lab32[2 * i] >= NN) ok = 0;
    __syncthreads();
    if (threadIdx.x == 0) g_lab64 = ok;
}

// ===========================================================================
// Kernel A: x_proj = x @ W_proj + b_proj (fp32) + fused hi/lo bf16 split
// ===========================================================================
__global__ void __launch_bounds__(256) proj_kernel(const float* __restrict__ x,
                                                   const float* __restrict__ W,
                                                   const float* __restrict__ bp) {
    __shared__ float xs[64 * 17];
    __shared__ float ws[16 * 65];
    const int tid = threadIdx.x;
    const int tx = tid & 15, ty = tid >> 4;
    const int rb = blockIdx.y * 64, cb = blockIdx.x * 64;

    float acc[4][4] = {};
    for (int kt = 0; kt < FEAT; kt += 16) {
        __syncthreads();
        for (int t = tid; t < 1024; t += 256) {
            int r = t >> 4, kk = t & 15;
            xs[r * 17 + kk] = x[(rb + r) * FEAT + kt + kk];
            int k2 = t >> 6, c = t & 63;
            ws[k2 * 65 + c] = W[(kt + k2) * HID + cb + c];
        }
        __syncthreads();
#pragma unroll
        for (int kk = 0; kk < 16; ++kk) {
            float a[4], b[4];
#pragma unroll
            for (int i = 0; i < 4; i++) a[i] = xs[(ty * 4 + i) * 17 + kk];
#pragma unroll
            for (int j = 0; j < 4; j++) b[j] = ws[kk * 65 + tx * 4 + j];
#pragma unroll
            for (int i = 0; i < 4; i++)
#pragma unroll
                for (int j = 0; j < 4; j++) acc[i][j] += a[i] * b[j];
        }
    }
#pragma unroll
    for (int i = 0; i < 4; i++) {
        int r = rb + ty * 4 + i;
#pragma unroll
        for (int j = 0; j < 4; j++) {
            int c = cb + tx * 4 + j;
            float val = acc[i][j] + bp[c];
            g_xp[r * HID + c] = val;
            float h = __bfloat162float(__float2bfloat16_rn(val));
            g_xphi[r * HID + c] = __float2bfloat16_rn(val);
            g_xplo[r * HID + c] = __float2bfloat16_rn(val - h);
        }
    }
}

// ===========================================================================
// Fused prep: single pass over M_n rows -> bf16 hi conversion AND
// v_n[row] = M_n[row,:] . mu_n (fp32).  grid (NN, 4): 64 rows per block.
// ===========================================================================
__global__ void __launch_bounds__(256) conv_mv_kernel(
    const float* __restrict__ means, const float* __restrict__ Mg) {
    __shared__ float mu[HID];
    const int n = blockIdx.x, rb = blockIdx.y * 64;
    const int tid = threadIdx.x, wid = tid >> 5, lane = tid & 31;
    mu[tid] = means[n * HID + tid];
    __syncthreads();
    const float* Mn = Mg + (size_t)n * HID * HID;
    __nv_bfloat16* Mh = g_Mhi + (size_t)n * HID * HID;
#pragma unroll
    for (int rr = 0; rr < 8; ++rr) {
        int row = rb + wid * 8 + rr;
        const float* mr = Mn + (size_t)row * HID;
        float s = 0.f;
#pragma unroll
        for (int p = 0; p < 2; ++p) {
            int i4 = lane + p * 32;
            float4 a = *(const float4*)&mr[i4 * 4];
            float4 b = *(const float4*)&mu[i4 * 4];
            s += a.x * b.x + a.y * b.y + a.z * b.z + a.w * b.w;
            float h0 = __bfloat162float(__float2bfloat16_rn(a.x));
            float h1 = __bfloat162float(__float2bfloat16_rn(a.y));
            float h2 = __bfloat162float(__float2bfloat16_rn(a.z));
            float h3 = __bfloat162float(__float2bfloat16_rn(a.w));
            *(unsigned long long*)&Mh[(size_t)row * HID + i4 * 4] =
                pack4bf(h0, h1, h2, h3);
        }
#pragma unroll
        for (int m = 16; m > 0; m >>= 1) s += __shfl_xor_sync(~0u, s, m);
        if (lane == 0) g_v[n * HID + row] = s;
    }
}

// c_n = mu_n . v_n  (deterministic tree reduce, one block per n)
__global__ void __launch_bounds__(256) c_kernel(const float* __restrict__ means) {
    __shared__ float red[256];
    const int n = blockIdx.x, tid = threadIdx.x;
    red[tid] = means[n * HID + tid] * g_v[n * HID + tid];
    __syncthreads();
#pragma unroll
    for (int s = 128; s > 0; s >>= 1) {
        if (tid < s) red[tid] += red[tid + s];
        __syncthreads();
    }
    if (tid == 0) g_c[n] = red[0];
}

// ===========================================================================
// Main kernel: Y = (Xh + Xl) @ Mh_n (2-term split); epilogue folds
// sum_j x*(Y - 2v) in fp32. grid = (NN, BB/128, 2); 8 warps (4m x 2n).
// SMEM/stage: Ah|Al (128x64 each) + Bh (128x64) = 48KB, double-buffered
// = 96KB -> 2 CTAs/SM. XOR-swizzled rows for conflict-free ldmatrix.
// ===========================================================================
#define KC       64
#define STG_B    49152

__global__ void __launch_bounds__(256, 2) center_mma_kernel() {
    extern __shared__ char smem[];
    const uint32_t sbase = smem_to_u32(smem);

    const int tid = threadIdx.x;
    const int wid = tid >> 5, lane = tid & 31;
    const int n  = blockIdx.x;
    const int b0 = blockIdx.y * 128;
    const int nh = blockIdx.z;                  // 0/1 column half

    const int wm = (wid & 3) * 32;              // warp m offset (0..96)
    const int wnh = wid >> 2;                   // warp n half (0/1)
    const int wn = wnh * 64;
    const int lr = lane & 15, lh = lane >> 4;
    const int gr = lane >> 2, qc = (lane & 3) * 2;

    const __nv_bfloat16* Ahg = g_xphi + (size_t)b0 * HID;
    const __nv_bfloat16* Alg = g_xplo + (size_t)b0 * HID;
    const __nv_bfloat16* Bhg = g_Mhi + ((size_t)n * HID + nh * 128) * HID;

    // stage one K-chunk (k0 = kc*64) into stage buffer s
    auto stage = [&](int kc, int s) {
        const int k0 = kc * KC;
        const uint32_t sb = sbase + s * STG_B;
#pragma unroll
        for (int it = 0; it < 12; ++it) {
            int t = tid + it * 256;             // 0..3071
            int buf = t >> 10;                  // 0 Ah, 1 Al, 2 Bh
            int rem = t & 1023;
            int r = rem >> 3, c16 = rem & 7;
            const __nv_bfloat16* src =
                (buf == 0 ? Ahg : buf == 1 ? Alg : Bhg)
                + (size_t)r * HID + k0 + c16 * 8;
            uint32_t dst = sb + ((buf << 10) + (r << 3) + (c16 ^ (r & 7))) * 16;
            cp_async16(dst, src);
        }
        CP_COMMIT();
    };

    float C[2][8][4];
#pragma unroll
    for (int a = 0; a < 2; a++)
#pragma unroll
        for (int b = 0; b < 8; b++)
#pragma unroll
            for (int c = 0; c < 4; c++) C[a][b][c] = 0.f;

    stage(0, 0);
    CP_WAIT0();
    __syncthreads();

    for (int kc = 0; kc < 4; ++kc) {
        if (kc < 3) stage(kc + 1, (kc + 1) & 1);
        const uint32_t sb = sbase + (kc & 1) * STG_B;
        const uint32_t oAh = sb, oAl = sb + 16384, oBh = sb + 32768;
#pragma unroll
        for (int ks = 0; ks < 4; ++ks) {
            uint32_t ah[2][4], al[2][4], bh[4][4];
#pragma unroll
            for (int mt = 0; mt < 2; ++mt) {
                int row = wm + mt * 16 + lr;
                uint32_t co = (uint32_t)(((2 * ks + lh) ^ (row & 7)) * 16 +
                                         row * 128);
                ldm_x4(ah[mt], oAh + co);
                ldm_x4(al[mt], oAl + co);
            }
#pragma unroll
            for (int nt = 0; nt < 4; ++nt) {
                int row = wn + nt * 16 + lr;
                uint32_t co = (uint32_t)(((2 * ks + lh) ^ (row & 7)) * 16 +
                                         row * 128);
                ldm_x4(bh[nt], oBh + co);
            }
#pragma unroll
            for (int mt = 0; mt < 2; ++mt)
#pragma unroll
                for (int nt = 0; nt < 4; ++nt) {
                    mma16816(C[mt][2 * nt],     ah[mt], bh[nt][0], bh[nt][2]);
                    mma16816(C[mt][2 * nt + 1], ah[mt], bh[nt][1], bh[nt][3]);
                    mma16816(C[mt][2 * nt],     al[mt], bh[nt][0], bh[nt][2]);
                    mma16816(C[mt][2 * nt + 1], al[mt], bh[nt][1], bh[nt][3]);
                }
        }
        if (kc < 3) {
            CP_WAIT0();
            __syncthreads();
        }
    }

    // epilogue: rs[row] = sum_{j in warp's 64 cols} x[row][j]*(Y[row][j]-2v[j])
    const float* vn = g_v + n * HID;
    float* part = g_part + (size_t)(nh * 2 + wnh) * BB * NN;
#pragma unroll
    for (int mt = 0; mt < 2; ++mt) {
        int row0 = b0 + wm + mt * 16 + gr;
        int row1 = row0 + 8;
        float rs0 = 0.f, rs1 = 0.f;
#pragma unroll
        for (int nt = 0; nt < 8; ++nt) {
            int j = nh * 128 + wn + nt * 8 + qc;
            float2 v2  = *(const float2*)&vn[j];
            float2 x0  = *(const float2*)&g_xp[(size_t)row0 * HID + j];
            float2 x1  = *(const float2*)&g_xp[(size_t)row1 * HID + j];
            rs0 += x0.x * (C[mt][nt][0] - 2.f * v2.x)
                 + x0.y * (C[mt][nt][1] - 2.f * v2.y);
            rs1 += x1.x * (C[mt][nt][2] - 2.f * v2.x)
                 + x1.y * (C[mt][nt][3] - 2.f * v2.y);
        }
        rs0 += __shfl_xor_sync(~0u, rs0, 1);
        rs0 += __shfl_xor_sync(~0u, rs0, 2);
        rs1 += __shfl_xor_sync(~0u, rs1, 1);
        rs1 += __shfl_xor_sync(~0u, rs1, 2);
        if ((lane & 3) == 0) {
            part[(size_t)row0 * NN + n] = rs0;
            part[(size_t)row1 * NN + n] = rs1;
        }
    }
}

// ===========================================================================
// finalize: dist = sqrt(sum of 4 partial slices + c_n + 1e-12)
// ===========================================================================
__global__ void __launch_bounds__(256) finalize_kernel(float* __restrict__ distout) {
    float* dp = distout ? distout : g_dist;
    int idx = blockIdx.x * 256 + threadIdx.x;     // 131072
    int nn = idx & (NN - 1);
    float dsq = g_part[idx] + g_part[BB * NN + idx]
              + g_part[2 * BB * NN + idx] + g_part[3 * BB * NN + idx]
              + g_c[nn];
    dp[idx] = sqrtf(dsq + 1e-12f);
}

// ===========================================================================
// Loss: single block, deterministic tree reduce over dist[b, label_b].
// ===========================================================================
__global__ void __launch_bounds__(1024) loss_kernel(
    const void* __restrict__ labels_raw,
    const float* __restrict__ distout,
    float* __restrict__ out) {
    __shared__ float red[1024];
    const float* dist = distout ? distout : g_dist;
    int b = threadIdx.x;
    int lab = g_lab64 ? (int)((const long long*)labels_raw)[b]
                      : ((const int*)labels_raw)[b];
    float d = dist[b * NN + lab];
    d = fminf(fmaxf(d, 1e-12f), 1e12f);
    red[b] = d;
    __syncthreads();
#pragma unroll
    for (int s = 512; s > 0; s >>= 1) {
        if (b < s) red[b] += red[b + s];
        __syncthreads();
    }
    if (b == 0)
        out[0] = red[0] * (1.0f / (float)BB) + (float)((double)(NN - 1) * 1e-12);
}

// ===========================================================================
extern "C" void kernel_launch(void* const* d_in, const int* in_sizes, int n_in,
                              void* d_out, int out_size) {
    const float* x     = (const float*)d_in[0];
    const void*  lab   = d_in[1];
    const float* W     = (const float*)d_in[2];
    const float* bp    = (const float*)d_in[3];
    const float* means = (const float*)d_in[4];
    const float* Mg    = (const float*)d_in[5];
    float* out = (float*)d_out;
    (void)in_sizes; (void)n_in;

    float* distout = out + 1;
    int loss_on = 1;
    if (out_size == BB * NN) { distout = out; loss_on = 0; }
    else if (out_size == 1)  { distout = nullptr; }

    cudaFuncSetAttribute(center_mma_kernel,
                         cudaFuncAttributeMaxDynamicSharedMemorySize,
                         2 * STG_B);

    if (loss_on) detect_labels_kernel<<<1, 512>>>((const int*)lab);
    conv_mv_kernel<<<dim3(NN, 4), 256>>>(means, Mg);
    proj_kernel<<<dim3(HID / 64, BB / 64), 256>>>(x, W, bp);
    c_kernel<<<NN, 256>>>(means);
    center_mma_kernel<<<dim3(NN, BB / 128, 2), 256, 2 * STG_B>>>();
    finalize_kernel<<<(BB * NN) / 256, 256>>>(distout);
    if (loss_on) loss_kernel<<<1, 1024>>>(lab, distout, out);
}

// round 16
// speedup vs baseline: 5.3594x; 1.3250x over previous
#include <cuda_runtime.h>
#include <cuda_fp16.h>
#include <math.h>
#include <stdint.h>

#define BB    1024
#define NN    128
#define FEAT  512
#define HID   256

// __device__ scratch (allocation-free rule)
__device__ float   g_xp  [BB * HID];
__device__ __half  g_xph [BB * HID];
__device__ __half  g_Mh  [NN * HID * HID];
__device__ float   g_v   [NN * HID];
__device__ float   g_cpart[NN * 4];
__device__ float   g_part[4 * BB * NN];   // slice = nh*2 + wn_half
__device__ float   g_dist[BB * NN];

// ===========================================================================
// helpers
// ===========================================================================
static __device__ __forceinline__ uint32_t smem_to_u32(const void* p) {
    uint32_t a;
    asm("{ .reg .u64 t; cvta.to.shared.u64 t, %1; cvt.u32.u64 %0, t; }"
        : "=r"(a) : "l"(p));
    return a;
}
static __device__ __forceinline__ void cp_async16(uint32_t dst, const void* src) {
    asm volatile("cp.async.cg.shared.global [%0], [%1], 16;"
                 :: "r"(dst), "l"(__cvta_generic_to_global(src)) : "memory");
}
#define CP_COMMIT() asm volatile("cp.async.commit_group;" ::: "memory")
#define CP_WAIT0()  asm volatile("cp.async.wait_group 0;" ::: "memory")
#define CP_WAIT1()  asm volatile("cp.async.wait_group 1;" ::: "memory")

static __device__ __forceinline__ void ldm_x4(uint32_t* r, uint32_t addr) {
    asm volatile("ldmatrix.sync.aligned.m8n8.x4.shared.b16 {%0,%1,%2,%3}, [%4];"
                 : "=r"(r[0]), "=r"(r[1]), "=r"(r[2]), "=r"(r[3]) : "r"(addr));
}
static __device__ __forceinline__ void mma16816h(float* c, const uint32_t* a,
                                                 uint32_t b0, uint32_t b1) {
    asm volatile(
        "mma.sync.aligned.m16n8k16.row.col.f32.f16.f16.f32 "
        "{%0,%1,%2,%3}, {%4,%5,%6,%7}, {%8,%9}, {%0,%1,%2,%3};"
        : "+f"(c[0]), "+f"(c[1]), "+f"(c[2]), "+f"(c[3])
        : "r"(a[0]), "r"(a[1]), "r"(a[2]), "r"(a[3]), "r"(b0), "r"(b1));
}
static __device__ __forceinline__ unsigned long long pack4h(float a, float b,
                                                            float c, float d) {
    __half2 p0 = __floats2half2_rn(a, b);
    __half2 p1 = __floats2half2_rn(c, d);
    unsigned lo = *(unsigned*)&p0, hi = *(unsigned*)&p1;
    unsigned long long r;
    asm("mov.b64 %0, {%1, %2};" : "=l"(r) : "r"(lo), "r"(hi));
    return r;
}

// ===========================================================================
// Kernel A: x_proj = x @ W_proj + b_proj (fp32) + fused fp16 copy
// ===========================================================================
__global__ void __launch_bounds__(256) proj_kernel(const float* __restrict__ x,
                                                   const float* __restrict__ W,
                                                   const float* __restrict__ bp) {
    __shared__ float xs[64 * 17];
    __shared__ float ws[16 * 65];
    const int tid = threadIdx.x;
    const int tx = tid & 15, ty = tid >> 4;
    const int rb = blockIdx.y * 64, cb = blockIdx.x * 64;

    float acc[4][4] = {};
    for (int kt = 0; kt < FEAT; kt += 16) {
        __syncthreads();
        for (int t = tid; t < 1024; t += 256) {
            int r = t >> 4, kk = t & 15;
            xs[r * 17 + kk] = x[(rb + r) * FEAT + kt + kk];
            int k2 = t >> 6, c = t & 63;
            ws[k2 * 65 + c] = W[(kt + k2) * HID + cb + c];
        }
        __syncthreads();
#pragma unroll
        for (int kk = 0; kk < 16; ++kk) {
            float a[4], b[4];
#pragma unroll
            for (int i = 0; i < 4; i++) a[i] = xs[(ty * 4 + i) * 17 + kk];
#pragma unroll
            for (int j = 0; j < 4; j++) b[j] = ws[kk * 65 + tx * 4 + j];
#pragma unroll
            for (int i = 0; i < 4; i++)
#pragma unroll
                for (int j = 0; j < 4; j++) acc[i][j] += a[i] * b[j];
        }
    }
#pragma unroll
    for (int i = 0; i < 4; i++) {
        int r = rb + ty * 4 + i;
#pragma unroll
        for (int j = 0; j < 4; j++) {
            int c = cb + tx * 4 + j;
            float val = acc[i][j] + bp[c];
            g_xp[r * HID + c] = val;
            g_xph[r * HID + c] = __float2half_rn(val);
        }
    }
}

// ===========================================================================
// Fused prep: single pass over M_n rows -> fp16 conversion, v_n row-dots,
// and per-block partial of c_n = mu.v.  grid (NN, 4): 64 rows per block.
// ===========================================================================
__global__ void __launch_bounds__(256) conv_mv_kernel(
    const float* __restrict__ means, const float* __restrict__ Mg) {
    __shared__ float mu[HID];
    __shared__ float sv[64];
    const int n = blockIdx.x, rb = blockIdx.y * 64;
    const int tid = threadIdx.x, wid = tid >> 5, lane = tid & 31;
    mu[tid] = means[n * HID + tid];
    __syncthreads();
    const float* Mn = Mg + (size_t)n * HID * HID;
    __half* Mh = g_Mh + (size_t)n * HID * HID;
#pragma unroll
    for (int rr = 0; rr < 8; ++rr) {
        int row = rb + wid * 8 + rr;
        const float* mr = Mn + (size_t)row * HID;
        float s = 0.f;
#pragma unroll
        for (int p = 0; p < 2; ++p) {
            int i4 = lane + p * 32;
            float4 a = *(const float4*)&mr[i4 * 4];
            float4 b = *(const float4*)&mu[i4 * 4];
            s += a.x * b.x + a.y * b.y + a.z * b.z + a.w * b.w;
            *(unsigned long long*)&Mh[(size_t)row * HID + i4 * 4] =
                pack4h(a.x, a.y, a.z, a.w);
        }
#pragma unroll
        for (int m = 16; m > 0; m >>= 1) s += __shfl_xor_sync(~0u, s, m);
        if (lane == 0) {
            g_v[n * HID + row] = s;
            sv[wid * 8 + rr] = s;
        }
    }
    __syncthreads();
    // block partial of c_n over these 64 rows (deterministic tree)
    __shared__ float red[64];
    if (tid < 64) red[tid] = mu[rb + tid] * sv[tid];
    __syncthreads();
#pragma unroll
    for (int s = 32; s > 0; s >>= 1) {
        if (tid < s) red[tid] += red[tid + s];
        __syncthreads();
    }
    if (tid == 0) g_cpart[n * 4 + blockIdx.y] = red[0];
}

// ===========================================================================
// Main kernel: Y = Xh @ Mh_n (fp16 single-term, fp32 accum); epilogue folds
// sum_j x*(Y - 2v) in fp32. grid = (NN, BB/128, 2); 8 warps (4m x 2n).
// 3-stage pipeline, KC=64: stage = A(16KB)+B(16KB) = 32KB, x3 = 96KB,
// 2 CTAs/SM. XOR-swizzled rows for conflict-free ldmatrix.
// ===========================================================================
#define KC       64
#define STG_B    32768
#define SMEM_CENTER (3 * STG_B)

__global__ void __launch_bounds__(256, 2) center_mma_kernel() {
    extern __shared__ char smem[];
    const uint32_t sbase = smem_to_u32(smem);

    const int tid = threadIdx.x;
    const int wid = tid >> 5, lane = tid & 31;
    const int n  = blockIdx.x;
    const int b0 = blockIdx.y * 128;
    const int nh = blockIdx.z;                  // 0/1 column half

    const int wm = (wid & 3) * 32;              // warp m offset (0..96)
    const int wnh = wid >> 2;                   // warp n half (0/1)
    const int wn = wnh * 64;
    const int lr = lane & 15, lh = lane >> 4;
    const int gr = lane >> 2, qc = (lane & 3) * 2;

    const __half* Ag = g_xph + (size_t)b0 * HID;
    const __half* Bg = g_Mh + ((size_t)n * HID + nh * 128) * HID;

    // stage one K-chunk (k0 = kc*64) into stage buffer s
    auto stage = [&](int kc, int s) {
        const int k0 = kc * KC;
        const uint32_t sb = sbase + s * STG_B;
#pragma unroll
        for (int it = 0; it < 8; ++it) {
            int t = tid + it * 256;             // 0..2047
            int buf = t >> 10;                  // 0 A, 1 B
            int rem = t & 1023;
            int r = rem >> 3, c16 = rem & 7;
            const __half* src = (buf == 0 ? Ag : Bg)
                + (size_t)r * HID + k0 + c16 * 8;
            uint32_t dst = sb + ((buf << 10) + (r << 3) + (c16 ^ (r & 7))) * 16;
            cp_async16(dst, src);
        }
        CP_COMMIT();
    };

    float C[2][8][4];
#pragma unroll
    for (int a = 0; a < 2; a++)
#pragma unroll
        for (int b = 0; b < 8; b++)
#pragma unroll
            for (int c = 0; c < 4; c++) C[a][b][c] = 0.f;

    stage(0, 0);
    stage(1, 1);

    for (int kc = 0; kc < 4; ++kc) {
        if (kc < 3) CP_WAIT1(); else CP_WAIT0();
        __syncthreads();
        if (kc < 2) stage(kc + 2, (kc + 2) % 3);   // buf (kc-1)%3 is free
        const uint32_t sb = sbase + (kc % 3) * STG_B;
        const uint32_t oA = sb, oB = sb + 16384;
#pragma unroll
        for (int ks = 0; ks < 4; ++ks) {
            uint32_t a[2][4], b[4][4];
#pragma unroll
            for (int mt = 0; mt < 2; ++mt) {
                int row = wm + mt * 16 + lr;
                uint32_t co = (uint32_t)(((2 * ks + lh) ^ (row & 7)) * 16 +
                                         row * 128);
                ldm_x4(a[mt], oA + co);
            }
#pragma unroll
            for (int nt = 0; nt < 4; ++nt) {
                int row = wn + nt * 16 + lr;
                uint32_t co = (uint32_t)(((2 * ks + lh) ^ (row & 7)) * 16 +
                                         row * 128);
                ldm_x4(b[nt], oB + co);
            }
#pragma unroll
            for (int mt = 0; mt < 2; ++mt)
#pragma unroll
                for (int nt = 0; nt < 4; ++nt) {
                    mma16816h(C[mt][2 * nt],     a[mt], b[nt][0], b[nt][2]);
                    mma16816h(C[mt][2 * nt + 1], a[mt], b[nt][1], b[nt][3]);
                }
        }
    }

    // epilogue: rs[row] = sum_{j in warp's 64 cols} x[row][j]*(Y[row][j]-2v[j])
    const float* vn = g_v + n * HID;
    float* part = g_part + (size_t)(nh * 2 + wnh) * BB * NN;
#pragma unroll
    for (int mt = 0; mt < 2; ++mt) {
        int row0 = b0 + wm + mt * 16 + gr;
        int row1 = row0 + 8;
        float rs0 = 0.f, rs1 = 0.f;
#pragma unroll
        for (int nt = 0; nt < 8; ++nt) {
            int j = nh * 128 + wn + nt * 8 + qc;
            float2 v2  = *(const float2*)&vn[j];
            float2 x0  = *(const float2*)&g_xp[(size_t)row0 * HID + j];
            float2 x1  = *(const float2*)&g_xp[(size_t)row1 * HID + j];
            rs0 += x0.x * (C[mt][nt][0] - 2.f * v2.x)
                 + x0.y * (C[mt][nt][1] - 2.f * v2.y);
            rs1 += x1.x * (C[mt][nt][2] - 2.f * v2.x)
                 + x1.y * (C[mt][nt][3] - 2.f * v2.y);
        }
        rs0 += __shfl_xor_sync(~0u, rs0, 1);
        rs0 += __shfl_xor_sync(~0u, rs0, 2);
        rs1 += __shfl_xor_sync(~0u, rs1, 1);
        rs1 += __shfl_xor_sync(~0u, rs1, 2);
        if ((lane & 3) == 0) {
            part[(size_t)row0 * NN + n] = rs0;
            part[(size_t)row1 * NN + n] = rs1;
        }
    }
}

// ===========================================================================
// finalize: dist = sqrt(sum of 4 partial slices + c_n + 1e-12)
// ===========================================================================
__global__ void __launch_bounds__(256) finalize_kernel(float* __restrict__ distout) {
    float* dp = distout ? distout : g_dist;
    int idx = blockIdx.x * 256 + threadIdx.x;     // 131072
    int nn = idx & (NN - 1);
    float cn = g_cpart[nn * 4 + 0] + g_cpart[nn * 4 + 1]
             + g_cpart[nn * 4 + 2] + g_cpart[nn * 4 + 3];
    float dsq = g_part[idx] + g_part[BB * NN + idx]
              + g_part[2 * BB * NN + idx] + g_part[3 * BB * NN + idx]
              + cn;
    dp[idx] = sqrtf(dsq + 1e-12f);
}

// ===========================================================================
// Loss: single block; fused label-dtype detection (int64 LE: odd words 0,
// even words < NN), then deterministic tree reduce over dist[b, label_b].
// ===========================================================================
__global__ void __launch_bounds__(1024) loss_kernel(
    const void* __restrict__ labels_raw,
    const float* __restrict__ distout,
    float* __restrict__ out) {
    __shared__ float red[1024];
    __shared__ int lab64;
    const float* dist = distout ? distout : g_dist;
    const int* lab32 = (const int*)labels_raw;
    int b = threadIdx.x;
    if (b == 0) lab64 = 1;
    __syncthreads();
    if (b < 512) {
        if (lab32[2 * b + 1] != 0 || (unsigned)lab32[2 * b] >= NN) lab64 = 0;
    }
    __syncthreads();
    int lab = lab64 ? (int)((const long long*)labels_raw)[b] : lab32[b];
    float d = dist[b * NN + lab];
    d = fminf(fmaxf(d, 1e-12f), 1e12f);
    red[b] = d;
    __syncthreads();
#pragma unroll
    for (int s = 512; s > 0; s >>= 1) {
        if (b < s) red[b] += red[b + s];
        __syncthreads();
    }
    if (b == 0)
        out[0] = red[0] * (1.0f / (float)BB) + (float)((double)(NN - 1) * 1e-12);
}

// ===========================================================================
extern "C" void kernel_launch(void* const* d_in, const int* in_sizes, int n_in,
                              void* d_out, int out_size) {
    const float* x     = (const float*)d_in[0];
    const void*  lab   = d_in[1];
    const float* W     = (const float*)d_in[2];
    const float* bp    = (const float*)d_in[3];
    const float* means = (const float*)d_in[4];
    const float* Mg    = (const float*)d_in[5];
    float* out = (float*)d_out;
    (void)in_sizes; (void)n_in;

    float* distout = out + 1;
    int loss_on = 1;
    if (out_size == BB * NN) { distout = out; loss_on = 0; }
    else if (out_size == 1)  { distout = nullptr; }

    cudaFuncSetAttribute(center_mma_kernel,
                         cudaFuncAttributeMaxDynamicSharedMemorySize,
                         SMEM_CENTER);

    conv_mv_kernel<<<dim3(NN, 4), 256>>>(means, Mg);
    proj_kernel<<<dim3(HID / 64, BB / 64), 256>>>(x, W, bp);
    center_mma_kernel<<<dim3(NN, BB / 128, 2), 256, SMEM_CENTER>>>();
    finalize_kernel<<<(BB * NN) / 256, 256>>>(distout);
    if (loss_on) loss_kernel<<<1, 1024>>>(lab, distout, out);
}

// round 17
// speedup vs baseline: 5.5140x; 1.0289x over previous
#include <cuda_runtime.h>
#include <cuda_fp16.h>
#include <math.h>
#include <stdint.h>

#define BB    1024
#define NN    128
#define FEAT  512
#define HID   256

// __device__ scratch (allocation-free rule)
__device__ __half  g_xph [BB * HID];
__device__ __half  g_Mh  [NN * HID * HID];
__device__ float   g_v   [NN * HID];
__device__ float   g_cpart[NN * 4];
__device__ float   g_part[4 * BB * NN];   // slice = nh*2 + wn_half
__device__ float   g_dist[BB * NN];

// ===========================================================================
// helpers
// ===========================================================================
static __device__ __forceinline__ uint32_t smem_to_u32(const void* p) {
    uint32_t a;
    asm("{ .reg .u64 t; cvta.to.shared.u64 t, %1; cvt.u32.u64 %0, t; }"
        : "=r"(a) : "l"(p));
    return a;
}
static __device__ __forceinline__ void cp_async16(uint32_t dst, const void* src) {
    asm volatile("cp.async.cg.shared.global [%0], [%1], 16;"
                 :: "r"(dst), "l"(__cvta_generic_to_global(src)) : "memory");
}
#define CP_COMMIT() asm volatile("cp.async.commit_group;" ::: "memory")
#define CP_WAIT0()  asm volatile("cp.async.wait_group 0;" ::: "memory")
#define CP_WAIT1()  asm volatile("cp.async.wait_group 1;" ::: "memory")

static __device__ __forceinline__ void ldm_x4(uint32_t* r, uint32_t addr) {
    asm volatile("ldmatrix.sync.aligned.m8n8.x4.shared.b16 {%0,%1,%2,%3}, [%4];"
                 : "=r"(r[0]), "=r"(r[1]), "=r"(r[2]), "=r"(r[3]) : "r"(addr));
}
static __device__ __forceinline__ void mma16816h(float* c, const uint32_t* a,
                                                 uint32_t b0, uint32_t b1) {
    asm volatile(
        "mma.sync.aligned.m16n8k16.row.col.f32.f16.f16.f32 "
        "{%0,%1,%2,%3}, {%4,%5,%6,%7}, {%8,%9}, {%0,%1,%2,%3};"
        : "+f"(c[0]), "+f"(c[1]), "+f"(c[2]), "+f"(c[3])
        : "r"(a[0]), "r"(a[1]), "r"(a[2]), "r"(a[3]), "r"(b0), "r"(b1));
}
static __device__ __forceinline__ unsigned long long pack4h(float a, float b,
                                                            float c, float d) {
    __half2 p0 = __floats2half2_rn(a, b);
    __half2 p1 = __floats2half2_rn(c, d);
    unsigned lo = *(unsigned*)&p0, hi = *(unsigned*)&p1;
    unsigned long long r;
    asm("mov.b64 %0, {%1, %2};" : "=l"(r) : "r"(lo), "r"(hi));
    return r;
}

// ===========================================================================
// Kernel A: x_proj = x @ W_proj + b_proj -> fp16 only.
// 64 rows x 32 cols per block -> grid (8, 16) = 128 blocks (was 64).
// ===========================================================================
__global__ void __launch_bounds__(256) proj_kernel(const float* __restrict__ x,
                                                   const float* __restrict__ W,
                                                   const float* __restrict__ bp) {
    __shared__ float xs[64 * 17];
    __shared__ float ws[16 * 33];
    const int tid = threadIdx.x;
    const int tx = tid & 15, ty = tid >> 4;     // tx: 16 col-pairs, ty: 16 row-quads
    const int rb = blockIdx.y * 64, cb = blockIdx.x * 32;

    float acc[4][2] = {};
    for (int kt = 0; kt < FEAT; kt += 16) {
        __syncthreads();
        for (int t = tid; t < 1024; t += 256) {
            int r = t >> 4, kk = t & 15;
            xs[r * 17 + kk] = x[(rb + r) * FEAT + kt + kk];
        }
        for (int t = tid; t < 512; t += 256) {
            int k2 = t >> 5, c = t & 31;
            ws[k2 * 33 + c] = W[(kt + k2) * HID + cb + c];
        }
        __syncthreads();
#pragma unroll
        for (int kk = 0; kk < 16; ++kk) {
            float a[4], b[2];
#pragma unroll
            for (int i = 0; i < 4; i++) a[i] = xs[(ty * 4 + i) * 17 + kk];
#pragma unroll
            for (int j = 0; j < 2; j++) b[j] = ws[kk * 33 + tx * 2 + j];
#pragma unroll
            for (int i = 0; i < 4; i++)
#pragma unroll
                for (int j = 0; j < 2; j++) acc[i][j] += a[i] * b[j];
        }
    }
#pragma unroll
    for (int i = 0; i < 4; i++) {
        int r = rb + ty * 4 + i;
        int c = cb + tx * 2;
        __half2 h = __floats2half2_rn(acc[i][0] + bp[c], acc[i][1] + bp[c + 1]);
        *(__half2*)&g_xph[r * HID + c] = h;
    }
}

// ===========================================================================
// Fused prep: single pass over M_n rows -> fp16 conversion, v_n row-dots,
// and per-block partial of c_n = mu.v.  grid (NN, 4): 64 rows per block.
// ===========================================================================
__global__ void __launch_bounds__(256) conv_mv_kernel(
    const float* __restrict__ means, const float* __restrict__ Mg) {
    __shared__ float mu[HID];
    __shared__ float sv[64];
    const int n = blockIdx.x, rb = blockIdx.y * 64;
    const int tid = threadIdx.x, wid = tid >> 5, lane = tid & 31;
    mu[tid] = means[n * HID + tid];
    __syncthreads();
    const float* Mn = Mg + (size_t)n * HID * HID;
    __half* Mh = g_Mh + (size_t)n * HID * HID;
#pragma unroll
    for (int rr = 0; rr < 8; ++rr) {
        int row = rb + wid * 8 + rr;
        const float* mr = Mn + (size_t)row * HID;
        float s = 0.f;
#pragma unroll
        for (int p = 0; p < 2; ++p) {
            int i4 = lane + p * 32;
            float4 a = *(const float4*)&mr[i4 * 4];
            float4 b = *(const float4*)&mu[i4 * 4];
            s += a.x * b.x + a.y * b.y + a.z * b.z + a.w * b.w;
            *(unsigned long long*)&Mh[(size_t)row * HID + i4 * 4] =
                pack4h(a.x, a.y, a.z, a.w);
        }
#pragma unroll
        for (int m = 16; m > 0; m >>= 1) s += __shfl_xor_sync(~0u, s, m);
        if (lane == 0) {
            g_v[n * HID + row] = s;
            sv[wid * 8 + rr] = s;
        }
    }
    __syncthreads();
    __shared__ float red[64];
    if (tid < 64) red[tid] = mu[rb + tid] * sv[tid];
    __syncthreads();
#pragma unroll
    for (int s = 32; s > 0; s >>= 1) {
        if (tid < s) red[tid] += red[tid + s];
        __syncthreads();
    }
    if (tid == 0) g_cpart[n * 4 + blockIdx.y] = red[0];
}

// ===========================================================================
// Main kernel: Y = Xh @ Mh_n (fp16 single-term, fp32 accum); epilogue folds
// sum_j x_h*(Y - 2v) in fp32 with x_h read from g_xph (fp16, half traffic).
// grid = (NN, BB/128, 2); 8 warps (4m x 2n). 3-stage pipeline, 2 CTAs/SM.
// ===========================================================================
#define KC       64
#define STG_B    32768
#define SMEM_CENTER (3 * STG_B)

__global__ void __launch_bounds__(256, 2) center_mma_kernel() {
    extern __shared__ char smem[];
    const uint32_t sbase = smem_to_u32(smem);

    const int tid = threadIdx.x;
    const int wid = tid >> 5, lane = tid & 31;
    const int n  = blockIdx.x;
    const int b0 = blockIdx.y * 128;
    const int nh = blockIdx.z;                  // 0/1 column half

    const int wm = (wid & 3) * 32;              // warp m offset (0..96)
    const int wnh = wid >> 2;                   // warp n half (0/1)
    const int wn = wnh * 64;
    const int lr = lane & 15, lh = lane >> 4;
    const int gr = lane >> 2, qc = (lane & 3) * 2;

    const __half* Ag = g_xph + (size_t)b0 * HID;
    const __half* Bg = g_Mh + ((size_t)n * HID + nh * 128) * HID;

    auto stage = [&](int kc, int s) {
        const int k0 = kc * KC;
        const uint32_t sb = sbase + s * STG_B;
#pragma unroll
        for (int it = 0; it < 8; ++it) {
            int t = tid + it * 256;             // 0..2047
            int buf = t >> 10;                  // 0 A, 1 B
            int rem = t & 1023;
            int r = rem >> 3, c16 = rem & 7;
            const __half* src = (buf == 0 ? Ag : Bg)
                + (size_t)r * HID + k0 + c16 * 8;
            uint32_t dst = sb + ((buf << 10) + (r << 3) + (c16 ^ (r & 7))) * 16;
            cp_async16(dst, src);
        }
        CP_COMMIT();
    };

    float C[2][8][4];
#pragma unroll
    for (int a = 0; a < 2; a++)
#pragma unroll
        for (int b = 0; b < 8; b++)
#pragma unroll
            for (int c = 0; c < 4; c++) C[a][b][c] = 0.f;

    stage(0, 0);
    stage(1, 1);

    for (int kc = 0; kc < 4; ++kc) {
        if (kc < 3) CP_WAIT1(); else CP_WAIT0();
        __syncthreads();
        if (kc < 2) stage(kc + 2, (kc + 2) % 3);
        const uint32_t sb = sbase + (kc % 3) * STG_B;
        const uint32_t oA = sb, oB = sb + 16384;
#pragma unroll
        for (int ks = 0; ks < 4; ++ks) {
            uint32_t a[2][4], b[4][4];
#pragma unroll
            for (int mt = 0; mt < 2; ++mt) {
                int row = wm + mt * 16 + lr;
                uint32_t co = (uint32_t)(((2 * ks + lh) ^ (row & 7)) * 16 +
                                         row * 128);
                ldm_x4(a[mt], oA + co);
            }
#pragma unroll
            for (int nt = 0; nt < 4; ++nt) {
                int row = wn + nt * 16 + lr;
                uint32_t co = (uint32_t)(((2 * ks + lh) ^ (row & 7)) * 16 +
                                         row * 128);
                ldm_x4(b[nt], oB + co);
            }
#pragma unroll
            for (int mt = 0; mt < 2; ++mt)
#pragma unroll
                for (int nt = 0; nt < 4; ++nt) {
                    mma16816h(C[mt][2 * nt],     a[mt], b[nt][0], b[nt][2]);
                    mma16816h(C[mt][2 * nt + 1], a[mt], b[nt][1], b[nt][3]);
                }
        }
    }

    // epilogue: rs[row] = sum_{j in warp's 64 cols} x_h[row][j]*(Y[row][j]-2v[j])
    const float* vn = g_v + n * HID;
    float* part = g_part + (size_t)(nh * 2 + wnh) * BB * NN;
#pragma unroll
    for (int mt = 0; mt < 2; ++mt) {
        int row0 = b0 + wm + mt * 16 + gr;
        int row1 = row0 + 8;
        float rs0 = 0.f, rs1 = 0.f;
#pragma unroll
        for (int nt = 0; nt < 8; ++nt) {
            int j = nh * 128 + wn + nt * 8 + qc;
            float2 v2 = *(const float2*)&vn[j];
            float2 x0 = __half22float2(*(const __half2*)&g_xph[(size_t)row0 * HID + j]);
            float2 x1 = __half22float2(*(const __half2*)&g_xph[(size_t)row1 * HID + j]);
            rs0 += x0.x * (C[mt][nt][0] - 2.f * v2.x)
                 + x0.y * (C[mt][nt][1] - 2.f * v2.y);
            rs1 += x1.x * (C[mt][nt][2] - 2.f * v2.x)
                 + x1.y * (C[mt][nt][3] - 2.f * v2.y);
        }
        rs0 += __shfl_xor_sync(~0u, rs0, 1);
        rs0 += __shfl_xor_sync(~0u, rs0, 2);
        rs1 += __shfl_xor_sync(~0u, rs1, 1);
        rs1 += __shfl_xor_sync(~0u, rs1, 2);
        if ((lane & 3) == 0) {
            part[(size_t)row0 * NN + n] = rs0;
            part[(size_t)row1 * NN + n] = rs1;
        }
    }
}

// ===========================================================================
// finalize: dist = sqrt(sum of 4 partial slices + c_n + 1e-12)
// ===========================================================================
__global__ void __launch_bounds__(256) finalize_kernel(float* __restrict__ distout) {
    float* dp = distout ? distout : g_dist;
    int idx = blockIdx.x * 256 + threadIdx.x;     // 131072
    int nn = idx & (NN - 1);
    float cn = g_cpart[nn * 4 + 0] + g_cpart[nn * 4 + 1]
             + g_cpart[nn * 4 + 2] + g_cpart[nn * 4 + 3];
    float dsq = g_part[idx] + g_part[BB * NN + idx]
              + g_part[2 * BB * NN + idx] + g_part[3 * BB * NN + idx]
              + cn;
    dp[idx] = sqrtf(dsq + 1e-12f);
}

// ===========================================================================
// Loss: single block; fused label-dtype detection (int64 LE: odd words 0,
// even words < NN), then deterministic tree reduce over dist[b, label_b].
// ===========================================================================
__global__ void __launch_bounds__(1024) loss_kernel(
    const void* __restrict__ labels_raw,
    const float* __restrict__ distout,
    float* __restrict__ out) {
    __shared__ float red[1024];
    __shared__ int lab64;
    const float* dist = distout ? distout : g_dist;
    const int* lab32 = (const int*)labels_raw;
    int b = threadIdx.x;
    if (b == 0) lab64 = 1;
    __syncthreads();
    if (b < 512) {
        if (lab32[2 * b + 1] != 0 || (unsigned)lab32[2 * b] >= NN) lab64 = 0;
    }
    __syncthreads();
    int lab = lab64 ? (int)((const long long*)labels_raw)[b] : lab32[b];
    float d = dist[b * NN + lab];
    d = fminf(fmaxf(d, 1e-12f), 1e12f);
    red[b] = d;
    __syncthreads();
#pragma unroll
    for (int s = 512; s > 0; s >>= 1) {
        if (b < s) red[b] += red[b + s];
        __syncthreads();
    }
    if (b == 0)
        out[0] = red[0] * (1.0f / (float)BB) + (float)((double)(NN - 1) * 1e-12);
}

// ===========================================================================
extern "C" void kernel_launch(void* const* d_in, const int* in_sizes, int n_in,
                              void* d_out, int out_size) {
    const float* x     = (const float*)d_in[0];
    const void*  lab   = d_in[1];
    const float* W     = (const float*)d_in[2];
    const float* bp    = (const float*)d_in[3];
    const float* means = (const float*)d_in[4];
    const float* Mg    = (const float*)d_in[5];
    float* out = (float*)d_out;
    (void)in_sizes; (void)n_in;

    float* distout = out + 1;
    int loss_on = 1;
    if (out_size == BB * NN) { distout = out; loss_on = 0; }
    else if (out_size == 1)  { distout = nullptr; }

    cudaFuncSetAttribute(center_mma_kernel,
                         cudaFuncAttributeMaxDynamicSharedMemorySize,
                         SMEM_CENTER);

    conv_mv_kernel<<<dim3(NN, 4), 256>>>(means, Mg);
    proj_kernel<<<dim3(HID / 32, BB / 64), 256>>>(x, W, bp);
    center_mma_kernel<<<dim3(NN, BB / 128, 2), 256, SMEM_CENTER>>>();
    finalize_kernel<<<(BB * NN) / 256, 256>>>(distout);
    if (loss_on) loss_kernel<<<1, 1024>>>(lab, distout, out);
}